// round 12
// baseline (speedup 1.0000x reference)
#include <cuda_runtime.h>
#include <cuda_bf16.h>
#include <math.h>

#define B_   256
#define IN_  64
#define HID_ 128
#define OUT_ 64
#define T_   1000
#define CH_  10
#define CL_  100

// ---------------- device scratch (static, allocation-free) ----------------
__device__ float g_xeff[(size_t)B_ * IN_ * T_];   // (b, i, t) effective x
__device__ float g_gxT [(size_t)B_ * IN_ * T_];   // (b, n, t) gamma_x
// per (b,t): [0:128)=gamma_h  [128:256)=A_z  [256:384)=A_r  [384:512)=A_h
__device__ float g_act [(size_t)B_ * T_ * 512];
__device__ float g_wzrh[128 * 384];               // packed [x;m] -> [z|r|h]
__device__ float g_bzrh[384];
__device__ __align__(16) float g_wzr [128 * 64 * 4]; // [j][q] = {wz_2q, wz_2q+1, wr_2q, wr_2q+1}
__device__ __align__(16) float g_whT [128 * 128];    // [j][k] = Whh[k][j]
__device__ float g_lastx[B_ * IN_ * CH_];
__device__ float g_hasx [B_ * IN_ * CH_];

__device__ __forceinline__ float sigf(float x) { return 1.0f / (1.0f + __expf(-x)); }
__device__ __forceinline__ float tanhfast(float x) {
    float e = __expf(-2.0f * fabsf(x));
    float r = (1.0f - e) / (1.0f + e);
    return copysignf(r, x);
}
// packed f32x2 FMA (sm_10x)
__device__ __forceinline__ unsigned long long ffma2(unsigned long long a,
                                                    unsigned long long b,
                                                    unsigned long long c) {
    unsigned long long d;
    asm("fma.rn.f32x2 %0, %1, %2, %3;" : "=l"(d) : "l"(a), "l"(b), "l"(c));
    return d;
}
__device__ __forceinline__ unsigned long long pack2(float w) {
    unsigned long long d;
    asm("mov.b64 %0, {%1, %1};" : "=l"(d) : "f"(w));
    return d;
}
__device__ __forceinline__ float2 up2(unsigned long long u) {
    return make_float2(__uint_as_float((unsigned)u),
                       __uint_as_float((unsigned)(u >> 32)));
}
__device__ __forceinline__ float hsum2(unsigned long long u) {
    float2 c = up2(u);
    return c.x + c.y;
}

// ---------------- pack weights ---------------------------------------------
__global__ void pack_kernel(const float* __restrict__ Wxz, const float* __restrict__ Wmz,
                            const float* __restrict__ bmz,
                            const float* __restrict__ Wxr, const float* __restrict__ Wmr,
                            const float* __restrict__ Wxh, const float* __restrict__ Wmh,
                            const float* __restrict__ bmh,
                            const float* __restrict__ Whz, const float* __restrict__ Whr,
                            const float* __restrict__ Whh) {
    int tid0 = blockIdx.x * blockDim.x + threadIdx.x;
    for (int idx = tid0; idx < 128 * 384; idx += gridDim.x * blockDim.x) {
        int k = idx / 384, n = idx % 384;
        int mat = n >> 7, j = n & 127;
        const float* Wx = (mat == 0) ? Wxz : ((mat == 1) ? Wxr : Wxh);
        const float* Wm = (mat == 0) ? Wmz : ((mat == 1) ? Wmr : Wmh);
        g_wzrh[idx] = (k < 64) ? Wx[k * 128 + j] : Wm[(k - 64) * 128 + j];
    }
    for (int n = tid0; n < 384; n += gridDim.x * blockDim.x) {
        int mat = n >> 7, j = n & 127;
        g_bzrh[n] = (mat == 0) ? bmz[j] : ((mat == 2) ? bmh[j] : 0.0f);
    }
    // zr interleaved pairs: [j][q] float4
    for (int idx = tid0; idx < 128 * 64; idx += gridDim.x * blockDim.x) {
        int j = idx >> 6, q = idx & 63;
        float4 v;
        v.x = Whz[(2 * q) * 128 + j];
        v.y = Whz[(2 * q + 1) * 128 + j];
        v.z = Whr[(2 * q) * 128 + j];
        v.w = Whr[(2 * q + 1) * 128 + j];
        *(float4*)&g_wzr[idx * 4] = v;
    }
    // h transposed
    for (int idx = tid0; idx < 128 * 128; idx += gridDim.x * blockDim.x) {
        int j = idx >> 7, k = idx & 127;
        g_whT[idx] = Whh[k * 128 + j];
    }
}

// ---------------- GEMM over feature-major A (f32x2, 128x128 tile) ----------
__global__ __launch_bounds__(256, 2)
void gemmT_kernel(const float* __restrict__ Ain,
                  const float* __restrict__ W_in, int ldw, int Ncols,
                  const float* __restrict__ bias_in,
                  int K, int actMode, int outMode, int outOff, int srcMode) {
    __shared__ __align__(16) float As[16 * 132];
    __shared__ __align__(16) float Bs[16 * 128];
    const float* Wp = srcMode ? g_wzrh : W_in;
    const float* bp = srcMode ? g_bzrh : bias_in;
    int b  = blockIdx.z;
    int t0 = blockIdx.y * 128;
    int n0 = blockIdx.x * 128;
    int tid = threadIdx.x;
    int f_l = tid >> 4, v = tid & 15;
    int ty  = tid >> 4, tx = tid & 15;

    unsigned long long acc[4][8];
#pragma unroll
    for (int i = 0; i < 4; i++)
#pragma unroll
        for (int j = 0; j < 8; j++) acc[i][j] = 0ull;

    for (int kbase = 0; kbase < K; kbase += 16) {
        int f = kbase + f_l;
        const float* rowp;
        if (srcMode == 0) {
            rowp = Ain + (size_t)2 * IN_ * T_ + (size_t)b * 3 * IN_ * T_ + (size_t)f * T_;
        } else {
            rowp = (f < 64) ? (g_xeff + (size_t)b * IN_ * T_ + (size_t)f * T_)
                            : (Ain + (size_t)IN_ * T_ + (size_t)b * 3 * IN_ * T_ + (size_t)(f - 64) * T_);
        }
#pragma unroll
        for (int h = 0; h < 2; ++h) {
            int tg = t0 + (v + 16 * h) * 4;
            float4 av = make_float4(0.f, 0.f, 0.f, 0.f);
            if (tg < T_) av = *(const float4*)(rowp + tg);
            *(float4*)&As[f_l * 132 + (v + 16 * h) * 4] = av;
        }
#pragma unroll
        for (int it = 0; it < 2; ++it) {
            int lin = tid + it * 256;
            int kq = lin >> 5, vq = lin & 31;
            int ng = n0 + vq * 4;
            float4 wv = make_float4(0.f, 0.f, 0.f, 0.f);
            if (ng < Ncols)
                wv = *(const float4*)(Wp + (size_t)(kbase + kq) * ldw + ng);
            *(float4*)&Bs[kq * 128 + vq * 4] = wv;
        }
        __syncthreads();
#pragma unroll
        for (int kk = 0; kk < 16; ++kk) {
            ulonglong2 a0 = *(const ulonglong2*)&As[kk * 132 + ty * 8];
            ulonglong2 a1 = *(const ulonglong2*)&As[kk * 132 + ty * 8 + 4];
            float4 bq0 = *(const float4*)&Bs[kk * 128 + tx * 8];
            float4 bq1 = *(const float4*)&Bs[kk * 128 + tx * 8 + 4];
            unsigned long long ap[4] = {a0.x, a0.y, a1.x, a1.y};
            unsigned long long bp8[8] = {pack2(bq0.x), pack2(bq0.y), pack2(bq0.z), pack2(bq0.w),
                                         pack2(bq1.x), pack2(bq1.y), pack2(bq1.z), pack2(bq1.w)};
#pragma unroll
            for (int i = 0; i < 4; i++)
#pragma unroll
                for (int j = 0; j < 8; j++) acc[i][j] = ffma2(ap[i], bp8[j], acc[i][j]);
        }
        __syncthreads();
    }
    if (n0 + tx * 8 >= Ncols) return;
    float bl[8];
#pragma unroll
    for (int j = 0; j < 8; j++) bl[j] = bp[n0 + tx * 8 + j];
#pragma unroll
    for (int ip = 0; ip < 4; ip++) {
        float va[2][8];
#pragma unroll
        for (int j = 0; j < 8; j++) {
            float2 c = up2(acc[ip][j]);
            va[0][j] = c.x; va[1][j] = c.y;
        }
#pragma unroll
        for (int s = 0; s < 2; ++s) {
            int tg = t0 + ty * 8 + ip * 2 + s;
            if (tg >= T_) continue;
            float vv[8];
#pragma unroll
            for (int j = 0; j < 8; j++) {
                float x = va[s][j] + bl[j];
                if (actMode == 1) x = __expf(-fmaxf(x, 0.0f));
                vv[j] = x;
            }
            if (outMode == 0) {
                float* dst = g_act + ((size_t)b * T_ + tg) * 512 + outOff + n0 + tx * 8;
                *(float4*)dst       = make_float4(vv[0], vv[1], vv[2], vv[3]);
                *(float4*)(dst + 4) = make_float4(vv[4], vv[5], vv[6], vv[7]);
            } else {
#pragma unroll
                for (int j = 0; j < 8; j++)
                    g_gxT[((size_t)b * 64 + n0 + tx * 8 + j) * T_ + tg] = vv[j];
            }
        }
    }
}

// ---------------- two-pass LOCF scan ---------------------------------------
__global__ void scanA_kernel(const float* __restrict__ input) {
    int tid = blockIdx.x * blockDim.x + threadIdx.x;
    int c = tid % CH_;
    int bi = tid / CH_;
    int b = bi >> 6, i = bi & 63;
    const float4* Xp = (const float4*)(input + ((size_t)(b * 3 + 0) * IN_ + i) * T_ + c * CL_);
    const float4* Mp = (const float4*)(input + ((size_t)(b * 3 + 1) * IN_ + i) * T_ + c * CL_);
    float last = 0.f, has = 0.f;
#pragma unroll 5
    for (int v = 0; v < CL_ / 4; ++v) {
        float4 x4 = Xp[v], m4 = Mp[v];
        if (m4.x > 0.f) { last = x4.x; has = 1.f; }
        if (m4.y > 0.f) { last = x4.y; has = 1.f; }
        if (m4.z > 0.f) { last = x4.z; has = 1.f; }
        if (m4.w > 0.f) { last = x4.w; has = 1.f; }
    }
    g_lastx[tid] = last;
    g_hasx[tid] = has;
}

__global__ void scanB_kernel(const float* __restrict__ input, const float* __restrict__ x_mean) {
    int tid = blockIdx.x * blockDim.x + threadIdx.x;
    int c = tid % CH_;
    int bi = tid / CH_;
    int b = bi >> 6, i = bi & 63;
    float xl = 0.f;
    for (int cc = c - 1; cc >= 0; --cc) {
        if (g_hasx[bi * CH_ + cc] > 0.f) { xl = g_lastx[bi * CH_ + cc]; break; }
    }
    const float4* Xp = (const float4*)(input + ((size_t)(b * 3 + 0) * IN_ + i) * T_ + c * CL_);
    const float4* Mp = (const float4*)(input + ((size_t)(b * 3 + 1) * IN_ + i) * T_ + c * CL_);
    const float4* Gp = (const float4*)(g_gxT + ((size_t)b * IN_ + i) * T_ + c * CL_);
    float4*       Op = (float4*)(g_xeff + ((size_t)b * IN_ + i) * T_ + c * CL_);
    float xm = x_mean[i];
#pragma unroll 5
    for (int v = 0; v < CL_ / 4; ++v) {
        float4 x4 = Xp[v], m4 = Mp[v], g4 = Gp[v];
        float4 o;
        if (m4.x > 0.f) { xl = x4.x; o.x = x4.x; } else { o.x = g4.x * xl + (1.f - g4.x) * xm; }
        if (m4.y > 0.f) { xl = x4.y; o.y = x4.y; } else { o.y = g4.y * xl + (1.f - g4.y) * xm; }
        if (m4.z > 0.f) { xl = x4.z; o.z = x4.z; } else { o.z = g4.z * xl + (1.f - g4.z) * xm; }
        if (m4.w > 0.f) { xl = x4.w; o.w = x4.w; } else { o.w = g4.w * xl + (1.f - g4.w) * xm; }
        Op[v] = o;
    }
}

// ---------------- persistent recurrence: k-split, 2 warps/SMSP -------------
// 256 threads = (column j = tid>>1, k-half h = tid&1). Thread (j,h) computes
// the k in [64h, 64h+64) partials of column j's z/r/h~ GEMVs for both batch
// rows; halves combine via shfl_xor(1) (adjacent lanes). Weights re-laid per
// virtual row vrow = 2j+h with padded strides (33 / 17 float4s) so LDS.128
// is conflict-free. 2 barriers per step, same as before.
__global__ __launch_bounds__(256, 1)
void recur_kernel(float* __restrict__ out) {
    extern __shared__ __align__(16) float sm[];
    float* Wzr = sm;                          // 256 * 33 float4 = 33792 floats
    float* Whs = Wzr + 256 * 33 * 4;          // 256 * 17 float4 = 17408 floats
    float* hq0 = Whs + 256 * 17 * 4;
    float* hq1 = hq0 + 128;
    float* hp0 = hq1 + 128;
    float* hp1 = hp0 + 128;

    int tid = threadIdx.x;
    int j = tid >> 1, h = tid & 1;
    int b0 = blockIdx.x * 2, b1 = b0 + 1;

    // relayout weights into smem: vrow = 2j+h owns its 32 (z/r) k-pair float4s
    for (int idx = tid; idx < 256 * 32; idx += 256) {
        int vrow = idx >> 5, qq = idx & 31;
        int jj = vrow >> 1, hh = vrow & 1;
        *(float4*)&Wzr[(vrow * 33 + qq) * 4] =
            *(const float4*)&g_wzr[(jj * 64 + hh * 32 + qq) * 4];
    }
    // Whh: vrow owns 16 float4 covering k in [64h, 64h+64)
    for (int idx = tid; idx < 256 * 16; idx += 256) {
        int vrow = idx >> 4, qq = idx & 15;
        int jj = vrow >> 1, hh = vrow & 1;
        *(float4*)&Whs[(vrow * 17 + qq) * 4] =
            *(const float4*)&g_whT[jj * 128 + hh * 64 + qq * 4];
    }
    __syncthreads();

    float* hs = out + (size_t)B_ * T_ * OUT_;

    const float* act0 = g_act + (size_t)b0 * T_ * 512 + j;
    const float* act1 = g_act + (size_t)b1 * T_ * 512 + j;

    float h0 = 0.f, h1 = 0.f;
    float cgh0 = act0[0], caz0 = act0[128], car0 = act0[256], cah0 = act0[384];
    float cgh1 = act1[0], caz1 = act1[128], car1 = act1[256], cah1 = act1[384];

    const ulonglong2* wz2 = (const ulonglong2*)(Wzr + tid * 33 * 4);
    const ulonglong2* wh2 = (const ulonglong2*)(Whs + tid * 17 * 4);
    const float* hqa = hq0 + 64 * h;
    const float* hqb = hq1 + 64 * h;
    const float* hpa = hp0 + 64 * h;
    const float* hpb = hp1 + 64 * h;

    for (int t = 0; t < T_; ++t) {
        float hh0 = cgh0 * h0;
        float hh1 = cgh1 * h1;
        if (!h) { hq0[j] = hh0; hq1[j] = hh1; }

        // prefetch next step activations (depth 1, as in the passing R6)
        float ngh0 = cgh0, naz0 = caz0, nar0 = car0, nah0 = cah0;
        float ngh1 = cgh1, naz1 = caz1, nar1 = car1, nah1 = cah1;
        if (t + 1 < T_) {
            const float* a0 = act0 + (size_t)(t + 1) * 512;
            const float* a1 = act1 + (size_t)(t + 1) * 512;
            ngh0 = a0[0]; naz0 = a0[128]; nar0 = a0[256]; nah0 = a0[384];
            ngh1 = a1[0]; naz1 = a1[128]; nar1 = a1[256]; nah1 = a1[384];
        }
        __syncthreads();

        // loop1: z/r partial GEMVs over own 64-k range (8 f32x2 chains)
        unsigned long long za0 = 0ull, za1 = 0ull, ra0 = 0ull, ra1 = 0ull;
        unsigned long long zb0 = 0ull, zb1 = 0ull, rb0 = 0ull, rb1 = 0ull;
#pragma unroll
        for (int q2 = 0; q2 < 16; ++q2) {
            ulonglong2 w0 = wz2[2 * q2];        // k-pair 2q2: {wz pair, wr pair}
            ulonglong2 w1 = wz2[2 * q2 + 1];    // k-pair 2q2+1
            ulonglong2 ha = *(const ulonglong2*)(hqa + 4 * q2);
            ulonglong2 hb = *(const ulonglong2*)(hqb + 4 * q2);
            za0 = ffma2(w0.x, ha.x, za0); ra0 = ffma2(w0.y, ha.x, ra0);
            za1 = ffma2(w0.x, hb.x, za1); ra1 = ffma2(w0.y, hb.x, ra1);
            zb0 = ffma2(w1.x, ha.y, zb0); rb0 = ffma2(w1.y, ha.y, rb0);
            zb1 = ffma2(w1.x, hb.y, zb1); rb1 = ffma2(w1.y, hb.y, rb1);
        }
        float zp0 = hsum2(za0) + hsum2(zb0);
        float zp1 = hsum2(za1) + hsum2(zb1);
        float rp0 = hsum2(ra0) + hsum2(rb0);
        float rp1 = hsum2(ra1) + hsum2(rb1);
        zp0 += __shfl_xor_sync(0xFFFFFFFFu, zp0, 1);
        zp1 += __shfl_xor_sync(0xFFFFFFFFu, zp1, 1);
        rp0 += __shfl_xor_sync(0xFFFFFFFFu, rp0, 1);
        rp1 += __shfl_xor_sync(0xFFFFFFFFu, rp1, 1);
        float z0 = sigf(zp0 + caz0);
        float z1 = sigf(zp1 + caz1);
        float r0 = sigf(rp0 + car0);
        float r1 = sigf(rp1 + car1);

        if (!h) { hp0[j] = r0 * hh0; hp1[j] = r1 * hh1; }
        __syncthreads();

        // loop2: h_tilde partial GEMV over own 64-k range (4 chains)
        unsigned long long ta0 = 0ull, tb0 = 0ull, ta1 = 0ull, tb1 = 0ull;
#pragma unroll
        for (int q4 = 0; q4 < 16; ++q4) {
            ulonglong2 wp = wh2[q4];
            ulonglong2 p0 = *(const ulonglong2*)(hpa + 4 * q4);
            ulonglong2 p1 = *(const ulonglong2*)(hpb + 4 * q4);
            ta0 = ffma2(wp.x, p0.x, ta0); tb0 = ffma2(wp.y, p0.y, tb0);
            ta1 = ffma2(wp.x, p1.x, ta1); tb1 = ffma2(wp.y, p1.y, tb1);
        }
        float tp0 = hsum2(ta0) + hsum2(tb0);
        float tp1 = hsum2(ta1) + hsum2(tb1);
        tp0 += __shfl_xor_sync(0xFFFFFFFFu, tp0, 1);
        tp1 += __shfl_xor_sync(0xFFFFFFFFu, tp1, 1);
        float ht0 = tanhfast(tp0 + cah0);
        float ht1 = tanhfast(tp1 + cah1);

        h0 = hh0 + z0 * (ht0 - hh0);
        h1 = hh1 + z1 * (ht1 - hh1);

        if (!h) {
            hs[((size_t)b0 * T_ + t) * 128 + j] = h0;
            hs[((size_t)b1 * T_ + t) * 128 + j] = h1;
        }

        cgh0 = ngh0; caz0 = naz0; car0 = nar0; cah0 = nah0;
        cgh1 = ngh1; caz1 = naz1; car1 = nar1; cah1 = nah1;
    }
}

// ---------------- y = sigmoid(hs @ W_hy + b_hy) (f32x2, reg-packed B) -------
__global__ __launch_bounds__(256)
void gemmY_kernel(const float* __restrict__ Why, const float* __restrict__ bhy,
                  float* __restrict__ out) {
    __shared__ __align__(16) float As[16 * 132];
    __shared__ __align__(16) float Bs[16 * 64];
    const float* A = out + (size_t)B_ * T_ * OUT_;
    size_t r0 = (size_t)blockIdx.x * 128;
    int tid = threadIdx.x;
    int ty = tid >> 4, tx = tid & 15;

    unsigned long long acc[4][4];
#pragma unroll
    for (int i = 0; i < 4; i++)
#pragma unroll
        for (int j = 0; j < 4; j++) acc[i][j] = 0ull;

    for (int kbase = 0; kbase < 128; kbase += 16) {
        {
            int row = tid >> 2, c = tid & 3;
#pragma unroll
            for (int rr = 0; rr < 2; ++rr) {
                int r = row + rr * 64;
                float4 av = *(const float4*)(A + (r0 + r) * 128 + kbase + c * 4);
                As[(c * 4 + 0) * 132 + r] = av.x;
                As[(c * 4 + 1) * 132 + r] = av.y;
                As[(c * 4 + 2) * 132 + r] = av.z;
                As[(c * 4 + 3) * 132 + r] = av.w;
            }
        }
        {
            int f_l = tid >> 4, v = tid & 15;
            *(float4*)&Bs[f_l * 64 + v * 4] =
                *(const float4*)(Why + (size_t)(kbase + f_l) * 64 + v * 4);
        }
        __syncthreads();
#pragma unroll
        for (int kk = 0; kk < 16; ++kk) {
            ulonglong2 a0 = *(const ulonglong2*)&As[kk * 132 + ty * 8];
            ulonglong2 a1 = *(const ulonglong2*)&As[kk * 132 + ty * 8 + 4];
            float4 bq = *(const float4*)&Bs[kk * 64 + tx * 4];
            unsigned long long ap[4] = {a0.x, a0.y, a1.x, a1.y};
            unsigned long long bp4[4] = {pack2(bq.x), pack2(bq.y), pack2(bq.z), pack2(bq.w)};
#pragma unroll
            for (int i = 0; i < 4; i++)
#pragma unroll
                for (int j = 0; j < 4; j++) acc[i][j] = ffma2(ap[i], bp4[j], acc[i][j]);
        }
        __syncthreads();
    }
    float bl[4];
#pragma unroll
    for (int j = 0; j < 4; j++) bl[j] = bhy[tx * 4 + j];
#pragma unroll
    for (int ip = 0; ip < 4; ip++) {
        float2 c0 = up2(acc[ip][0]), c1 = up2(acc[ip][1]);
        float2 c2 = up2(acc[ip][2]), c3 = up2(acc[ip][3]);
        float va[2][4] = {{c0.x, c1.x, c2.x, c3.x}, {c0.y, c1.y, c2.y, c3.y}};
#pragma unroll
        for (int s = 0; s < 2; ++s) {
            size_t rg = r0 + ty * 8 + ip * 2 + s;
            float4 vo;
            vo.x = sigf(va[s][0] + bl[0]);
            vo.y = sigf(va[s][1] + bl[1]);
            vo.z = sigf(va[s][2] + bl[2]);
            vo.w = sigf(va[s][3] + bl[3]);
            *(float4*)(out + rg * 64 + tx * 4) = vo;
        }
    }
}

// ---------------- launch ----------------------------------------------------
extern "C" void kernel_launch(void* const* d_in, const int* in_sizes, int n_in,
                              void* d_out, int out_size) {
    const float* input  = (const float*)d_in[0];
    const float* x_mean = (const float*)d_in[1];
    const float* W_dg_x = (const float*)d_in[2];
    const float* b_dg_x = (const float*)d_in[3];
    const float* W_dg_h = (const float*)d_in[4];
    const float* b_dg_h = (const float*)d_in[5];
    const float* W_xz   = (const float*)d_in[6];
    const float* W_hz   = (const float*)d_in[7];
    const float* W_mz   = (const float*)d_in[8];
    const float* b_mz   = (const float*)d_in[9];
    const float* W_xr   = (const float*)d_in[10];
    const float* W_hr   = (const float*)d_in[11];
    const float* W_mr   = (const float*)d_in[12];
    const float* W_xh   = (const float*)d_in[13];
    const float* W_hh   = (const float*)d_in[14];
    const float* W_mh   = (const float*)d_in[15];
    const float* b_mh   = (const float*)d_in[16];
    const float* W_hy   = (const float*)d_in[17];
    const float* b_hy   = (const float*)d_in[18];
    float* out = (float*)d_out;

    // Wzr 256*33*16B + Whs 256*17*16B + 4*128 floats
    const int recur_smem = 256 * 33 * 16 + 256 * 17 * 16 + 4 * 128 * 4;

    static bool attr_set = false;
    if (!attr_set) {
        cudaFuncSetAttribute(recur_kernel, cudaFuncAttributeMaxDynamicSharedMemorySize,
                             recur_smem);
        attr_set = true;
    }

    pack_kernel<<<32, 256>>>(W_xz, W_mz, b_mz, W_xr, W_mr, W_xh, W_mh, b_mh,
                             W_hz, W_hr, W_hh);

    // chunk summaries for LOCF (depends only on input)
    scanA_kernel<<<(B_ * IN_ * CH_) / 256, 256>>>(input);

    // gamma_x: K=64, N=64 -> g_gxT (b,n,t)
    gemmT_kernel<<<dim3(1, 8, B_), 256>>>(input, W_dg_x, 64, 64, b_dg_x,
                                          64, /*act*/1, /*out*/1, 0, /*src*/0);
    // gamma_h: K=64, N=128 -> g_act[0:128)
    gemmT_kernel<<<dim3(1, 8, B_), 256>>>(input, W_dg_h, 128, 128, b_dg_h,
                                          64, 1, 0, 0, 0);
    // LOCF apply -> g_xeff
    scanB_kernel<<<(B_ * IN_ * CH_) / 256, 256>>>(input, x_mean);
    // A_zrh: K=128, N=384 -> g_act[128:512)
    gemmT_kernel<<<dim3(3, 8, B_), 256>>>(input, nullptr, 384, 384, nullptr,
                                          128, 0, 0, 128, 1);
    // recurrence -> hs region of d_out
    recur_kernel<<<128, 256, recur_smem>>>(out);
    // y -> ys region of d_out
    gemmY_kernel<<<(B_ * T_) / 128, 256>>>(W_hy, b_hy, out);
}

// round 13
// speedup vs baseline: 1.2335x; 1.2335x over previous
#include <cuda_runtime.h>
#include <cuda_bf16.h>
#include <math.h>

#define B_   256
#define IN_  64
#define HID_ 128
#define OUT_ 64
#define T_   1000
#define CH_  10
#define CL_  100

// ---------------- device scratch (static, allocation-free) ----------------
__device__ float g_xeff[(size_t)B_ * IN_ * T_];   // (b, i, t) effective x
__device__ float g_gxT [(size_t)B_ * IN_ * T_];   // (b, n, t) gamma_x
// per (b,t): [0:128)=gamma_h  [128:256)=A_z  [256:384)=A_r  [384:512)=A_h
__device__ float g_act [(size_t)B_ * T_ * 512];
__device__ float g_wzrh[128 * 384];               // packed [x;m] -> [z|r|h]
__device__ float g_bzrh[384];
__device__ float g_lastx[B_ * IN_ * CH_];
__device__ float g_hasx [B_ * IN_ * CH_];

__device__ __forceinline__ float sigf(float x) { return 1.0f / (1.0f + __expf(-x)); }
__device__ __forceinline__ float tanhfast(float x) {
    float e = __expf(-2.0f * fabsf(x));
    float r = (1.0f - e) / (1.0f + e);
    return copysignf(r, x);
}
// packed f32x2 FMA (sm_10x)
__device__ __forceinline__ unsigned long long ffma2(unsigned long long a,
                                                    unsigned long long b,
                                                    unsigned long long c) {
    unsigned long long d;
    asm("fma.rn.f32x2 %0, %1, %2, %3;" : "=l"(d) : "l"(a), "l"(b), "l"(c));
    return d;
}
__device__ __forceinline__ unsigned long long pack2(float w) {
    unsigned long long d;
    asm("mov.b64 %0, {%1, %1};" : "=l"(d) : "f"(w));
    return d;
}
__device__ __forceinline__ float2 up2(unsigned long long u) {
    return make_float2(__uint_as_float((unsigned)u),
                       __uint_as_float((unsigned)(u >> 32)));
}

// ---------------- GEMM body (f32x2, 128x128 tile) ---------------------------
// C[b][t][n] = sum_f A[b][f][t] * W[f][n]  (+bias, +activation)
__device__ __forceinline__
void gemmT_body(const float* __restrict__ Ain,
                const float* __restrict__ W_in, int ldw, int Ncols,
                const float* __restrict__ bias_in,
                int K, int actMode, int outMode, int outOff, int srcMode,
                int n0, int t0, int b) {
    __shared__ __align__(16) float As[16 * 132];
    __shared__ __align__(16) float Bs[16 * 128];
    const float* Wp = srcMode ? g_wzrh : W_in;
    const float* bp = srcMode ? g_bzrh : bias_in;
    int tid = threadIdx.x;
    int f_l = tid >> 4, v = tid & 15;
    int ty  = tid >> 4, tx = tid & 15;

    unsigned long long acc[4][8];
#pragma unroll
    for (int i = 0; i < 4; i++)
#pragma unroll
        for (int j = 0; j < 8; j++) acc[i][j] = 0ull;

    for (int kbase = 0; kbase < K; kbase += 16) {
        int f = kbase + f_l;
        const float* rowp;
        if (srcMode == 0) {
            rowp = Ain + (size_t)2 * IN_ * T_ + (size_t)b * 3 * IN_ * T_ + (size_t)f * T_;
        } else {
            rowp = (f < 64) ? (g_xeff + (size_t)b * IN_ * T_ + (size_t)f * T_)
                            : (Ain + (size_t)IN_ * T_ + (size_t)b * 3 * IN_ * T_ + (size_t)(f - 64) * T_);
        }
#pragma unroll
        for (int h = 0; h < 2; ++h) {
            int tg = t0 + (v + 16 * h) * 4;
            float4 av = make_float4(0.f, 0.f, 0.f, 0.f);
            if (tg < T_) av = *(const float4*)(rowp + tg);
            *(float4*)&As[f_l * 132 + (v + 16 * h) * 4] = av;
        }
#pragma unroll
        for (int it = 0; it < 2; ++it) {
            int lin = tid + it * 256;
            int kq = lin >> 5, vq = lin & 31;
            int ng = n0 + vq * 4;
            float4 wv = make_float4(0.f, 0.f, 0.f, 0.f);
            if (ng < Ncols)
                wv = *(const float4*)(Wp + (size_t)(kbase + kq) * ldw + ng);
            *(float4*)&Bs[kq * 128 + vq * 4] = wv;
        }
        __syncthreads();
#pragma unroll
        for (int kk = 0; kk < 16; ++kk) {
            ulonglong2 a0 = *(const ulonglong2*)&As[kk * 132 + ty * 8];
            ulonglong2 a1 = *(const ulonglong2*)&As[kk * 132 + ty * 8 + 4];
            float4 bq0 = *(const float4*)&Bs[kk * 128 + tx * 8];
            float4 bq1 = *(const float4*)&Bs[kk * 128 + tx * 8 + 4];
            unsigned long long ap[4] = {a0.x, a0.y, a1.x, a1.y};
            unsigned long long bp8[8] = {pack2(bq0.x), pack2(bq0.y), pack2(bq0.z), pack2(bq0.w),
                                         pack2(bq1.x), pack2(bq1.y), pack2(bq1.z), pack2(bq1.w)};
#pragma unroll
            for (int i = 0; i < 4; i++)
#pragma unroll
                for (int j = 0; j < 8; j++) acc[i][j] = ffma2(ap[i], bp8[j], acc[i][j]);
        }
        __syncthreads();
    }
    if (n0 + tx * 8 >= Ncols) return;
    float bl[8];
#pragma unroll
    for (int j = 0; j < 8; j++) bl[j] = bp[n0 + tx * 8 + j];
#pragma unroll
    for (int ip = 0; ip < 4; ip++) {
        float va[2][8];
#pragma unroll
        for (int j = 0; j < 8; j++) {
            float2 c = up2(acc[ip][j]);
            va[0][j] = c.x; va[1][j] = c.y;
        }
#pragma unroll
        for (int s = 0; s < 2; ++s) {
            int tg = t0 + ty * 8 + ip * 2 + s;
            if (tg >= T_) continue;
            float vv[8];
#pragma unroll
            for (int j = 0; j < 8; j++) {
                float x = va[s][j] + bl[j];
                if (actMode == 1) x = __expf(-fmaxf(x, 0.0f));
                vv[j] = x;
            }
            if (outMode == 0) {
                float* dst = g_act + ((size_t)b * T_ + tg) * 512 + outOff + n0 + tx * 8;
                *(float4*)dst       = make_float4(vv[0], vv[1], vv[2], vv[3]);
                *(float4*)(dst + 4) = make_float4(vv[4], vv[5], vv[6], vv[7]);
            } else {
#pragma unroll
                for (int j = 0; j < 8; j++)
                    g_gxT[((size_t)b * 64 + n0 + tx * 8 + j) * T_ + tg] = vv[j];
            }
        }
    }
}

__global__ __launch_bounds__(256, 2)
void gemmT_kernel(const float* __restrict__ Ain,
                  const float* __restrict__ W_in, int ldw, int Ncols,
                  const float* __restrict__ bias_in,
                  int K, int actMode, int outMode, int outOff, int srcMode) {
    gemmT_body(Ain, W_in, ldw, Ncols, bias_in, K, actMode, outMode, outOff, srcMode,
               blockIdx.x * 128, blockIdx.y * 128, blockIdx.z);
}

// ---------------- merged: pack weights + LOCF chunk summaries --------------
__global__ void packScanA_kernel(const float* __restrict__ input,
                                 const float* __restrict__ Wxz, const float* __restrict__ Wmz,
                                 const float* __restrict__ bmz,
                                 const float* __restrict__ Wxr, const float* __restrict__ Wmr,
                                 const float* __restrict__ Wxh, const float* __restrict__ Wmh,
                                 const float* __restrict__ bmh) {
    if (blockIdx.x < 32) {
        int tid0 = blockIdx.x * 256 + threadIdx.x;
        const int stride = 32 * 256;
        for (int idx = tid0; idx < 128 * 384; idx += stride) {
            int k = idx / 384, n = idx % 384;
            int mat = n >> 7, j = n & 127;
            const float* Wx = (mat == 0) ? Wxz : ((mat == 1) ? Wxr : Wxh);
            const float* Wm = (mat == 0) ? Wmz : ((mat == 1) ? Wmr : Wmh);
            g_wzrh[idx] = (k < 64) ? Wx[k * 128 + j] : Wm[(k - 64) * 128 + j];
        }
        for (int n = tid0; n < 384; n += stride) {
            int mat = n >> 7, j = n & 127;
            g_bzrh[n] = (mat == 0) ? bmz[j] : ((mat == 2) ? bmh[j] : 0.0f);
        }
    } else {
        int tid = (blockIdx.x - 32) * 256 + threadIdx.x;   // < B*IN*CH
        int c = tid % CH_;
        int bi = tid / CH_;
        int b = bi >> 6, i = bi & 63;
        const float4* Xp = (const float4*)(input + ((size_t)(b * 3 + 0) * IN_ + i) * T_ + c * CL_);
        const float4* Mp = (const float4*)(input + ((size_t)(b * 3 + 1) * IN_ + i) * T_ + c * CL_);
        float last = 0.f, has = 0.f;
#pragma unroll 5
        for (int v = 0; v < CL_ / 4; ++v) {
            float4 x4 = Xp[v], m4 = Mp[v];
            if (m4.x > 0.f) { last = x4.x; has = 1.f; }
            if (m4.y > 0.f) { last = x4.y; has = 1.f; }
            if (m4.z > 0.f) { last = x4.z; has = 1.f; }
            if (m4.w > 0.f) { last = x4.w; has = 1.f; }
        }
        g_lastx[tid] = last;
        g_hasx[tid] = has;
    }
}

// ---------------- merged: gamma_h GEMM + LOCF apply (scanB) ----------------
__global__ __launch_bounds__(256, 2)
void ghScanB_kernel(const float* __restrict__ input,
                    const float* __restrict__ Wdgh, const float* __restrict__ bdgh,
                    const float* __restrict__ x_mean) {
    if (blockIdx.x < 2048) {
        // gamma_h: K=64, N=128 -> g_act[0:128)
        gemmT_body(input, Wdgh, 128, 128, bdgh, 64, /*act*/1, /*out*/0, 0, /*src*/0,
                   /*n0*/0, /*t0*/(blockIdx.x & 7) * 128, /*b*/blockIdx.x >> 3);
    } else {
        int tid = (blockIdx.x - 2048) * 256 + threadIdx.x;
        int c = tid % CH_;
        int bi = tid / CH_;
        int b = bi >> 6, i = bi & 63;
        float xl = 0.f;
        for (int cc = c - 1; cc >= 0; --cc) {
            if (g_hasx[bi * CH_ + cc] > 0.f) { xl = g_lastx[bi * CH_ + cc]; break; }
        }
        const float4* Xp = (const float4*)(input + ((size_t)(b * 3 + 0) * IN_ + i) * T_ + c * CL_);
        const float4* Mp = (const float4*)(input + ((size_t)(b * 3 + 1) * IN_ + i) * T_ + c * CL_);
        const float4* Gp = (const float4*)(g_gxT + ((size_t)b * IN_ + i) * T_ + c * CL_);
        float4*       Op = (float4*)(g_xeff + ((size_t)b * IN_ + i) * T_ + c * CL_);
        float xm = x_mean[i];
#pragma unroll 5
        for (int v = 0; v < CL_ / 4; ++v) {
            float4 x4 = Xp[v], m4 = Mp[v], g4 = Gp[v];
            float4 o;
            if (m4.x > 0.f) { xl = x4.x; o.x = x4.x; } else { o.x = g4.x * xl + (1.f - g4.x) * xm; }
            if (m4.y > 0.f) { xl = x4.y; o.y = x4.y; } else { o.y = g4.y * xl + (1.f - g4.y) * xm; }
            if (m4.z > 0.f) { xl = x4.z; o.z = x4.z; } else { o.z = g4.z * xl + (1.f - g4.z) * xm; }
            if (m4.w > 0.f) { xl = x4.w; o.w = x4.w; } else { o.w = g4.w * xl + (1.f - g4.w) * xm; }
            Op[v] = o;
        }
    }
}

// ---------------- persistent recurrence: exact R2 structure ----------------
// 128 threads; thread tid owns output column tid for BOTH rows. Weights
// transposed into smem (stride 132). 16 independent fmaf chains. 2 barriers.
__global__ __launch_bounds__(128, 1)
void recur_kernel(const float* __restrict__ Whz, const float* __restrict__ Whr,
                  const float* __restrict__ Whh, float* __restrict__ out) {
    extern __shared__ float sm[];
    float* Wz   = sm;
    float* Wr   = Wz + 128 * 132;
    float* Wh   = Wr + 128 * 132;
    float* hbuf = Wh + 128 * 132;
    float* rbuf = hbuf + 2 * 2 * 128;

    int tid = threadIdx.x;
    int b0 = blockIdx.x * 2, b1 = b0 + 1;

    for (int idx = tid; idx < 128 * 128; idx += 128) {
        int k = idx >> 7, j = idx & 127;
        Wz[j * 132 + k] = Whz[idx];
        Wr[j * 132 + k] = Whr[idx];
        Wh[j * 132 + k] = Whh[idx];
    }
    __syncthreads();

    float* hs = out + (size_t)B_ * T_ * OUT_;

    const float* act0 = g_act + (size_t)b0 * T_ * 512 + tid;
    const float* act1 = g_act + (size_t)b1 * T_ * 512 + tid;

    float h0 = 0.f, h1 = 0.f;
    float gh0 = act0[0], az0 = act0[128], ar0 = act0[256], ah0 = act0[384];
    float gh1 = act1[0], az1 = act1[128], ar1 = act1[256], ah1 = act1[384];

    const float4* wz4 = (const float4*)(Wz + tid * 132);
    const float4* wr4 = (const float4*)(Wr + tid * 132);
    const float4* wh4 = (const float4*)(Wh + tid * 132);

    for (int t = 0; t < T_; ++t) {
        int p = t & 1;
        float* hq = hbuf + p * 256;
        float* hp = rbuf + p * 256;

        float hh0 = gh0 * h0;
        float hh1 = gh1 * h1;
        hq[tid] = hh0;
        hq[128 + tid] = hh1;

        float ngh0 = gh0, naz0 = az0, nar0 = ar0, nah0 = ah0;
        float ngh1 = gh1, naz1 = az1, nar1 = ar1, nah1 = ah1;
        if (t + 1 < T_) {
            const float* a0 = act0 + (size_t)(t + 1) * 512;
            const float* a1 = act1 + (size_t)(t + 1) * 512;
            ngh0 = a0[0]; naz0 = a0[128]; nar0 = a0[256]; nah0 = a0[384];
            ngh1 = a1[0]; naz1 = a1[128]; nar1 = a1[256]; nah1 = a1[384];
        }
        __syncthreads();

        float za0 = az0, zb0 = 0.f, zc0 = 0.f, zd0 = 0.f;
        float za1 = az1, zb1 = 0.f, zc1 = 0.f, zd1 = 0.f;
        float ra0 = ar0, rb0 = 0.f, rc0 = 0.f, rd0 = 0.f;
        float ra1 = ar1, rb1 = 0.f, rc1 = 0.f, rd1 = 0.f;
        const float4* h0v = (const float4*)hq;
        const float4* h1v = (const float4*)(hq + 128);
#pragma unroll
        for (int k4 = 0; k4 < 32; ++k4) {
            float4 wz = wz4[k4], wr = wr4[k4];
            float4 a0 = h0v[k4], a1 = h1v[k4];
            za0 = fmaf(wz.x, a0.x, za0); zb0 = fmaf(wz.y, a0.y, zb0);
            zc0 = fmaf(wz.z, a0.z, zc0); zd0 = fmaf(wz.w, a0.w, zd0);
            za1 = fmaf(wz.x, a1.x, za1); zb1 = fmaf(wz.y, a1.y, zb1);
            zc1 = fmaf(wz.z, a1.z, zc1); zd1 = fmaf(wz.w, a1.w, zd1);
            ra0 = fmaf(wr.x, a0.x, ra0); rb0 = fmaf(wr.y, a0.y, rb0);
            rc0 = fmaf(wr.z, a0.z, rc0); rd0 = fmaf(wr.w, a0.w, rd0);
            ra1 = fmaf(wr.x, a1.x, ra1); rb1 = fmaf(wr.y, a1.y, rb1);
            rc1 = fmaf(wr.z, a1.z, rc1); rd1 = fmaf(wr.w, a1.w, rd1);
        }
        float z0 = sigf((za0 + zb0) + (zc0 + zd0));
        float z1 = sigf((za1 + zb1) + (zc1 + zd1));
        float r0 = sigf((ra0 + rb0) + (rc0 + rd0));
        float r1 = sigf((ra1 + rb1) + (rc1 + rd1));

        hp[tid] = r0 * hh0;
        hp[128 + tid] = r1 * hh1;
        __syncthreads();

        float ta0 = ah0, tb0 = 0.f, tc0 = 0.f, td0 = 0.f;
        float ta1 = ah1, tb1 = 0.f, tc1 = 0.f, td1 = 0.f;
        const float4* p0v = (const float4*)hp;
        const float4* p1v = (const float4*)(hp + 128);
#pragma unroll
        for (int k4 = 0; k4 < 32; ++k4) {
            float4 wh = wh4[k4];
            float4 a0 = p0v[k4], a1 = p1v[k4];
            ta0 = fmaf(wh.x, a0.x, ta0); tb0 = fmaf(wh.y, a0.y, tb0);
            tc0 = fmaf(wh.z, a0.z, tc0); td0 = fmaf(wh.w, a0.w, td0);
            ta1 = fmaf(wh.x, a1.x, ta1); tb1 = fmaf(wh.y, a1.y, tb1);
            tc1 = fmaf(wh.z, a1.z, tc1); td1 = fmaf(wh.w, a1.w, td1);
        }
        float ht0 = tanhfast((ta0 + tb0) + (tc0 + td0));
        float ht1 = tanhfast((ta1 + tb1) + (tc1 + td1));

        h0 = (1.f - z0) * hh0 + z0 * ht0;
        h1 = (1.f - z1) * hh1 + z1 * ht1;

        hs[((size_t)b0 * T_ + t) * 128 + tid] = h0;
        hs[((size_t)b1 * T_ + t) * 128 + tid] = h1;

        gh0 = ngh0; az0 = naz0; ar0 = nar0; ah0 = nah0;
        gh1 = ngh1; az1 = naz1; ar1 = nar1; ah1 = nah1;
    }
}

// ---------------- y = sigmoid(hs @ W_hy + b_hy) (f32x2, reg-packed B) -------
__global__ __launch_bounds__(256)
void gemmY_kernel(const float* __restrict__ Why, const float* __restrict__ bhy,
                  float* __restrict__ out) {
    __shared__ __align__(16) float As[16 * 132];
    __shared__ __align__(16) float Bs[16 * 64];
    const float* A = out + (size_t)B_ * T_ * OUT_;
    size_t r0 = (size_t)blockIdx.x * 128;
    int tid = threadIdx.x;
    int ty = tid >> 4, tx = tid & 15;

    unsigned long long acc[4][4];
#pragma unroll
    for (int i = 0; i < 4; i++)
#pragma unroll
        for (int j = 0; j < 4; j++) acc[i][j] = 0ull;

    for (int kbase = 0; kbase < 128; kbase += 16) {
        {
            int row = tid >> 2, c = tid & 3;
#pragma unroll
            for (int rr = 0; rr < 2; ++rr) {
                int r = row + rr * 64;
                float4 av = *(const float4*)(A + (r0 + r) * 128 + kbase + c * 4);
                As[(c * 4 + 0) * 132 + r] = av.x;
                As[(c * 4 + 1) * 132 + r] = av.y;
                As[(c * 4 + 2) * 132 + r] = av.z;
                As[(c * 4 + 3) * 132 + r] = av.w;
            }
        }
        {
            int f_l = tid >> 4, v = tid & 15;
            *(float4*)&Bs[f_l * 64 + v * 4] =
                *(const float4*)(Why + (size_t)(kbase + f_l) * 64 + v * 4);
        }
        __syncthreads();
#pragma unroll
        for (int kk = 0; kk < 16; ++kk) {
            ulonglong2 a0 = *(const ulonglong2*)&As[kk * 132 + ty * 8];
            ulonglong2 a1 = *(const ulonglong2*)&As[kk * 132 + ty * 8 + 4];
            float4 bq = *(const float4*)&Bs[kk * 64 + tx * 4];
            unsigned long long ap[4] = {a0.x, a0.y, a1.x, a1.y};
            unsigned long long bp4[4] = {pack2(bq.x), pack2(bq.y), pack2(bq.z), pack2(bq.w)};
#pragma unroll
            for (int i = 0; i < 4; i++)
#pragma unroll
                for (int j = 0; j < 4; j++) acc[i][j] = ffma2(ap[i], bp4[j], acc[i][j]);
        }
        __syncthreads();
    }
    float bl[4];
#pragma unroll
    for (int j = 0; j < 4; j++) bl[j] = bhy[tx * 4 + j];
#pragma unroll
    for (int ip = 0; ip < 4; ip++) {
        float2 c0 = up2(acc[ip][0]), c1 = up2(acc[ip][1]);
        float2 c2 = up2(acc[ip][2]), c3 = up2(acc[ip][3]);
        float va[2][4] = {{c0.x, c1.x, c2.x, c3.x}, {c0.y, c1.y, c2.y, c3.y}};
#pragma unroll
        for (int s = 0; s < 2; ++s) {
            size_t rg = r0 + ty * 8 + ip * 2 + s;
            float4 vo;
            vo.x = sigf(va[s][0] + bl[0]);
            vo.y = sigf(va[s][1] + bl[1]);
            vo.z = sigf(va[s][2] + bl[2]);
            vo.w = sigf(va[s][3] + bl[3]);
            *(float4*)(out + rg * 64 + tx * 4) = vo;
        }
    }
}

// ---------------- launch ----------------------------------------------------
extern "C" void kernel_launch(void* const* d_in, const int* in_sizes, int n_in,
                              void* d_out, int out_size) {
    const float* input  = (const float*)d_in[0];
    const float* x_mean = (const float*)d_in[1];
    const float* W_dg_x = (const float*)d_in[2];
    const float* b_dg_x = (const float*)d_in[3];
    const float* W_dg_h = (const float*)d_in[4];
    const float* b_dg_h = (const float*)d_in[5];
    const float* W_xz   = (const float*)d_in[6];
    const float* W_hz   = (const float*)d_in[7];
    const float* W_mz   = (const float*)d_in[8];
    const float* b_mz   = (const float*)d_in[9];
    const float* W_xr   = (const float*)d_in[10];
    const float* W_hr   = (const float*)d_in[11];
    const float* W_mr   = (const float*)d_in[12];
    const float* W_xh   = (const float*)d_in[13];
    const float* W_hh   = (const float*)d_in[14];
    const float* W_mh   = (const float*)d_in[15];
    const float* b_mh   = (const float*)d_in[16];
    const float* W_hy   = (const float*)d_in[17];
    const float* b_hy   = (const float*)d_in[18];
    float* out = (float*)d_out;

    const int recur_smem = (3 * 128 * 132 + 2 * 2 * 128 + 2 * 2 * 128) * 4;  // 206848

    static bool attr_set = false;
    if (!attr_set) {
        cudaFuncSetAttribute(recur_kernel, cudaFuncAttributeMaxDynamicSharedMemorySize,
                             recur_smem);
        attr_set = true;
    }

    // k1: pack combined weights + LOCF chunk summaries (32 + 640 blocks)
    packScanA_kernel<<<32 + (B_ * IN_ * CH_) / 256, 256>>>(
        input, W_xz, W_mz, b_mz, W_xr, W_mr, W_xh, W_mh, b_mh);

    // k2: gamma_x GEMM: K=64, N=64 -> g_gxT (b,n,t)
    gemmT_kernel<<<dim3(1, 8, B_), 256>>>(input, W_dg_x, 64, 64, b_dg_x,
                                          64, /*act*/1, /*out*/1, 0, /*src*/0);

    // k3: gamma_h GEMM + LOCF apply (2048 + 640 blocks)
    ghScanB_kernel<<<2048 + (B_ * IN_ * CH_) / 256, 256>>>(input, W_dg_h, b_dg_h, x_mean);

    // k4: A_zrh GEMM: K=128, N=384 -> g_act[128:512)   (profiled slot)
    gemmT_kernel<<<dim3(3, 8, B_), 256>>>(input, nullptr, 384, 384, nullptr,
                                          128, 0, 0, 128, 1);

    // k5: recurrence -> hs region of d_out
    recur_kernel<<<128, 128, recur_smem>>>(W_hz, W_hr, W_hh, out);

    // k6: y -> ys region of d_out
    gemmY_kernel<<<(B_ * T_) / 128, 256>>>(W_hy, b_hy, out);
}